// round 5
// baseline (speedup 1.0000x reference)
#include <cuda_runtime.h>
#include <cuda_fp16.h>
#include <stdint.h>

// Problem constants
#define IC    384
#define OCC   384
#define NB    32
#define IH    64
#define IW    64
#define OH    32
#define OW    32
#define KTOT  (IC * 9)          // 3456
#define NWEI  (OCC * KTOT)      // 1327104
#define NTOT  (NB * OH * OW)    // 32768

// GEMM tiling: CTA = 128(M) x 256(N) x 64(K), 8 warps of 64x64
#define BM    128
#define BN    256
#define BK    64
#define NKB   (KTOT / BK)       // 54
#define S     3                 // cp.async pipeline stages
#define ASTR  72                // halves per A smem row (144B = 9 x 16B units, odd -> LDSM CF)
#define BSTR  264               // halves per B smem row (528B = 33 units, odd -> LDSM CF)
#define ABYTES (BM * ASTR * 2)  // 18432
#define BBYTES (BK * BSTR * 2)  // 33792
#define STAGE  (ABYTES + BBYTES)          // 52224
#define SMEM_TOTAL (S * STAGE)            // 156672

#define KWSZ ((size_t)NB * IC * 66 * 32)  // halves per kw plane

// Scratch (device globals: allocation-free contract)
__device__ float  g_alpha;
__device__ float  g_part[256];
__device__ __half g_wq[(size_t)NKB * OCC * BK];  // [kb64][oc][64] ternary fp16
__device__ __half g_xq[3 * KWSZ];                // [kw][b][ic][row 0..65][ox 0..31]

// ---------------------------------------------------------------------------
// Stage 1: deterministic |w| reduction -> alpha
// ---------------------------------------------------------------------------
__global__ void abssum_part(const float* __restrict__ w) {
    __shared__ float sm[256];
    const int tid = threadIdx.x;
    float s = 0.f;
    for (int i = blockIdx.x * 256 + tid; i < NWEI; i += 256 * 256)
        s += fabsf(w[i]);
    sm[tid] = s;
    __syncthreads();
    #pragma unroll
    for (int o = 128; o > 0; o >>= 1) {
        if (tid < o) sm[tid] += sm[tid + o];
        __syncthreads();
    }
    if (tid == 0) g_part[blockIdx.x] = sm[0];
}

__global__ void abssum_fin() {
    __shared__ float sm[256];
    const int tid = threadIdx.x;
    sm[tid] = g_part[tid];
    __syncthreads();
    #pragma unroll
    for (int o = 128; o > 0; o >>= 1) {
        if (tid < o) sm[tid] += sm[tid + o];
        __syncthreads();
    }
    if (tid == 0) g_alpha = sm[0] / (float)NWEI;
}

// ---------------------------------------------------------------------------
// Stage 2a: ternary quantize, OIHW -> [kb64][oc][64] fp16
// ---------------------------------------------------------------------------
__global__ void quantize_w(const float* __restrict__ w) {
    const int j = blockIdx.x * 256 + threadIdx.x;
    if (j >= NWEI) return;
    const float thr = 0.001f * g_alpha;
    const int oc  = j / KTOT;
    const int r   = j - oc * KTOT;
    const int tap = r / IC;
    const int ic  = r - tap * IC;
    const float wv = w[oc * KTOT + ic * 9 + tap];     // OIHW linear
    const float q = (wv > thr) ? 1.f : ((wv < -thr) ? -1.f : 0.f);
    const int kb = tap * 6 + (ic >> 6);
    g_wq[((size_t)kb * OCC + oc) * BK + (ic & 63)] = __float2half_rn(q);
}

// ---------------------------------------------------------------------------
// Stage 2b: x fp32 -> fp16, deinterleaved by kw tap, padded halo rows.
//   xq[kw][bc][row][ox] = x[bc][row-1][2*ox-1+kw]  (OOB -> 0)
// ---------------------------------------------------------------------------
__global__ void prep_x(const float* __restrict__ x) {
    const int idx = blockIdx.x * 256 + threadIdx.x;
    const int t = idx & 15;             // handles ox pair (2t, 2t+1)
    const int r = idx >> 4;             // row id over NB*IC*65
    if (r >= NB * IC * 65) return;
    const int iy = r % 65 - 1;          // -1..63
    const int bc = r / 65;              // b*IC + ic
    const size_t orow = ((size_t)bc * 66 + (iy + 1)) * 32 + 2 * t;

    __half2 h0, h1, h2;
    if (iy < 0) {
        h0 = h1 = h2 = __floats2half2_rn(0.f, 0.f);
    } else {
        const float* xr = x + ((size_t)bc * IH + iy) * IW;
        const float4 v = *reinterpret_cast<const float4*>(xr + 4 * t);
        const float prev = (t > 0) ? xr[4 * t - 1] : 0.f;
        h0 = __floats2half2_rn(prev, v.y);   // kw=0: ix = 2ox-1
        h1 = __floats2half2_rn(v.x,  v.z);   // kw=1: ix = 2ox
        h2 = __floats2half2_rn(v.y,  v.w);   // kw=2: ix = 2ox+1
    }
    *reinterpret_cast<__half2*>(g_xq + 0 * KWSZ + orow) = h0;
    *reinterpret_cast<__half2*>(g_xq + 1 * KWSZ + orow) = h1;
    *reinterpret_cast<__half2*>(g_xq + 2 * KWSZ + orow) = h2;
}

// ---------------------------------------------------------------------------
// Stage 3: implicit-GEMM conv, cp.async S=3 + ldmatrix + mma.sync
//   per-warp 64x64, fragments double-buffered across k16 steps
// ---------------------------------------------------------------------------
__device__ __forceinline__ void cp16(uint32_t dst, const void* src) {
    asm volatile("cp.async.cg.shared.global [%0], [%1], 16;\n"
                 :: "r"(dst), "l"(src) : "memory");
}
__device__ __forceinline__ void ldsmA(uint32_t* f, uint32_t addr) {
    asm volatile("ldmatrix.sync.aligned.m8n8.x4.shared.b16 {%0,%1,%2,%3}, [%4];\n"
                 : "=r"(f[0]), "=r"(f[1]), "=r"(f[2]), "=r"(f[3]) : "r"(addr));
}
__device__ __forceinline__ void ldsmBT(uint32_t* f, uint32_t addr) {
    asm volatile("ldmatrix.sync.aligned.m8n8.x4.trans.shared.b16 {%0,%1,%2,%3}, [%4];\n"
                 : "=r"(f[0]), "=r"(f[1]), "=r"(f[2]), "=r"(f[3]) : "r"(addr));
}

__global__ __launch_bounds__(256, 1)
void conv_mma3(const float* __restrict__ bias, float* __restrict__ out)
{
    extern __shared__ char smem_raw[];
    const uint32_t sbase = (uint32_t)__cvta_generic_to_shared(smem_raw);

    const int tid  = threadIdx.x;
    const int lane = tid & 31;
    const int wid  = tid >> 5;
    const int wm   = wid >> 2;          // 0..1
    const int wn   = wid & 3;           // 0..3

    const int m_tile = blockIdx.x % 3;  // adjacent bids share the B slab (L2)
    const int n_tile = blockIdx.x / 3;
    const int oc0  = m_tile * BM;
    const int n0   = n_tile * BN;
    const int bimg = n0 >> 10;          // BN=256 divides 1024
    const int pos0 = n0 & 1023;
    const int oy0  = pos0 >> 5;

    // ---- cp.async invariants (affine in chunk index j) ----
    // A: chunk = tid + 256j (j<4): m = chunk>>3, c = chunk&7 (c const over j)
    const int am0 = tid >> 3, ac = tid & 7;
    const size_t   aoff0 = (size_t)(oc0 + am0) * BK + ac * 8;        // + kb*384*64
    const uint32_t adst0 = sbase + (uint32_t)(am0 * ASTR + ac * 8) * 2;
    // strides per j: src +32*64 halves, dst +32*ASTR*2 bytes
    // B: chunk = tid + 256j (j<8): kB = chunk>>5, nc = chunk&31 (nc const over j)
    const int kB0 = tid >> 5, nc = tid & 31;
    const int oyc = oy0 + (nc >> 2);
    const size_t   boff0 = ((size_t)kB0 * 66 + 2 * oyc) * 32 + (nc & 3) * 8;
    const uint32_t bdst0 = sbase + (uint32_t)ABYTES + (uint32_t)(kB0 * BSTR + nc * 8) * 2;
    // strides per j: src +8*66*32 halves, dst +8*BSTR*2 bytes
    const size_t bplane0 = (size_t)bimg * IC * (66 * 32);

    // ---- ldmatrix per-lane invariants ----
    const int arow  = wm * 64 + ((lane >> 3) & 1) * 8 + (lane & 7);
    const int acol  = (lane >> 4) * 8;
    const int brow  = ((lane >> 3) & 1) * 8 + (lane & 7);
    const int bcolh = wn * 64 + (lane >> 4) * 8;

    float acc[4][8][4];
    #pragma unroll
    for (int i = 0; i < 4; i++)
        #pragma unroll
        for (int j = 0; j < 8; j++)
            #pragma unroll
            for (int c = 0; c < 4; c++)
                acc[i][j][c] = 0.f;

    auto issue = [&](int kb, int s) {
        const int tap = kb / 6;                  // 0..8
        const int icb = (kb - tap * 6) << 6;
        const int kh  = tap / 3;
        const int kw  = tap - kh * 3;
        const __half* wsrc = g_wq + (size_t)kb * (OCC * BK) + aoff0;
        const __half* xsrc = g_xq + (size_t)kw * KWSZ + bplane0
                           + (size_t)icb * (66 * 32) + kh * 32 + boff0;
        const uint32_t st = (uint32_t)(s * STAGE);
        #pragma unroll
        for (int j = 0; j < 4; j++)
            cp16(adst0 + st + j * (32 * ASTR * 2), wsrc + j * (32 * BK));
        #pragma unroll
        for (int j = 0; j < 8; j++)
            cp16(bdst0 + st + j * (8 * BSTR * 2), xsrc + j * (size_t)(8 * 66 * 32));
        asm volatile("cp.async.commit_group;\n" ::: "memory");
    };

    auto compute = [&](int s) {
        const uint32_t aB = sbase + (uint32_t)(s * STAGE);
        const uint32_t bB = aB + (uint32_t)ABYTES;
        uint32_t a[2][4][4], b[2][4][4];

        auto loadfrag = [&](int step, int buf) {
            #pragma unroll
            for (int ms = 0; ms < 4; ms++)
                ldsmA(a[buf][ms],
                      aB + (uint32_t)(((arow + ms * 16) * ASTR) + step * 16 + acol) * 2);
            #pragma unroll
            for (int nb = 0; nb < 4; nb++)
                ldsmBT(b[buf][nb],
                       bB + (uint32_t)((step * 16 + brow) * BSTR + bcolh + nb * 16) * 2);
        };

        loadfrag(0, 0);
        #pragma unroll
        for (int step = 0; step < 4; step++) {
            const int cur = step & 1;
            if (step < 3) loadfrag(step + 1, cur ^ 1);
            #pragma unroll
            for (int ms = 0; ms < 4; ms++)
                #pragma unroll
                for (int ns = 0; ns < 8; ns++)
                    asm volatile(
                        "mma.sync.aligned.m16n8k16.row.col.f32.f16.f16.f32 "
                        "{%0,%1,%2,%3}, {%4,%5,%6,%7}, {%8,%9}, {%0,%1,%2,%3};\n"
                        : "+f"(acc[ms][ns][0]), "+f"(acc[ms][ns][1]),
                          "+f"(acc[ms][ns][2]), "+f"(acc[ms][ns][3])
                        : "r"(a[cur][ms][0]), "r"(a[cur][ms][1]),
                          "r"(a[cur][ms][2]), "r"(a[cur][ms][3]),
                          "r"(b[cur][ns >> 1][(ns & 1) * 2]),
                          "r"(b[cur][ns >> 1][(ns & 1) * 2 + 1]));
        }
    };

    // prologue: fill S-1 stages
    issue(0, 0); issue(1, 1);

    #pragma unroll 1
    for (int kb = 0; kb < NKB; kb++) {
        asm volatile("cp.async.wait_group %0;\n" :: "n"(S - 2) : "memory");
        __syncthreads();
        if (kb + (S - 1) < NKB)
            issue(kb + (S - 1), (kb + (S - 1)) % S);
        else
            asm volatile("cp.async.commit_group;\n" ::: "memory");  // keep group count uniform
        compute(kb % S);
    }

    // epilogue: out = alpha*acc + bias   (NCHW per-batch [oc][pos] row-major)
    const float alpha = g_alpha;
    const int g  = lane >> 2;
    const int tq = lane & 3;
    float* ob = out + (size_t)bimg * OCC * (OH * OW);
    #pragma unroll
    for (int ms = 0; ms < 4; ms++) {
        const int oc_a = oc0 + wm * 64 + ms * 16 + g;
        const int oc_b = oc_a + 8;
        const float ba = bias[oc_a];
        const float bc = bias[oc_b];
        #pragma unroll
        for (int ns = 0; ns < 8; ns++) {
            const int pcol = pos0 + wn * 64 + ns * 8 + tq * 2;
            float2 v0, v1;
            v0.x = alpha * acc[ms][ns][0] + ba;
            v0.y = alpha * acc[ms][ns][1] + ba;
            v1.x = alpha * acc[ms][ns][2] + bc;
            v1.y = alpha * acc[ms][ns][3] + bc;
            *reinterpret_cast<float2*>(ob + (size_t)oc_a * (OH * OW) + pcol) = v0;
            *reinterpret_cast<float2*>(ob + (size_t)oc_b * (OH * OW) + pcol) = v1;
        }
    }
}

// ---------------------------------------------------------------------------
extern "C" void kernel_launch(void* const* d_in, const int* in_sizes, int n_in,
                              void* d_out, int out_size)
{
    (void)in_sizes; (void)n_in; (void)out_size;
    const float* x      = (const float*)d_in[0];
    const float* weight = (const float*)d_in[1];
    const float* bias   = (const float*)d_in[2];
    float* out = (float*)d_out;

    cudaFuncSetAttribute(conv_mma3, cudaFuncAttributeMaxDynamicSharedMemorySize, SMEM_TOTAL);

    abssum_part<<<256, 256>>>(weight);
    abssum_fin<<<1, 256>>>();
    quantize_w<<<(NWEI + 255) / 256, 256>>>(weight);
    prep_x<<<(NB * IC * 65 * 16 + 255) / 256, 256>>>(x);
    conv_mma3<<<(NTOT / BN) * 3, 256, SMEM_TOTAL>>>(bias, out);
}

// round 7
// speedup vs baseline: 1.0271x; 1.0271x over previous
#include <cuda_runtime.h>
#include <cuda_fp16.h>
#include <stdint.h>

// Problem constants
#define IC    384
#define OCC   384
#define NB    32
#define IH    64
#define IW    64
#define OH    32
#define OW    32
#define KTOT  (IC * 9)          // 3456
#define NWEI  (OCC * KTOT)      // 1327104
#define NTOT  (NB * OH * OW)    // 32768

// GEMM tiling: CTA = 128(M) x 128(N) x 64(K), 8 warps of 64x32, occupancy 2
#define BM    128
#define BN    128
#define BK    64
#define NKB   (KTOT / BK)       // 54
#define NTILE ((NTOT / BN) * 3) // 768 logical tiles
#define GRID  296               // persistent: 2 CTAs x 148 SMs
#define S     3                 // cp.async pipeline stages
#define ASTR  72                // halves per A smem row (144B = 9 odd 16B units, LDSM CF)
#define BSTR  136               // halves per B smem row (272B = 17 odd units, LDSM CF)
#define ABYTES (BM * ASTR * 2)  // 18432
#define BBYTES (BK * BSTR * 2)  // 17408
#define STAGE  (ABYTES + BBYTES)          // 35840
#define SMEM_TOTAL (S * STAGE)            // 107520 (x2 CTAs = 210KB/SM)

#define KWSZ ((size_t)NB * IC * 66 * 32)  // halves per kw plane

// Scratch (device globals: allocation-free contract)
__device__ float  g_alpha;
__device__ float  g_part[256];
__device__ __half g_wq[(size_t)NKB * OCC * BK];  // [kb64][oc][64] ternary fp16
__device__ __half g_xq[3 * KWSZ];                // [kw][b][ic][row 0..65][ox 0..31]

// ---------------------------------------------------------------------------
// Stage 1: deterministic |w| reduction -> alpha
// ---------------------------------------------------------------------------
__global__ void abssum_part(const float* __restrict__ w) {
    __shared__ float sm[256];
    const int tid = threadIdx.x;
    float s = 0.f;
    for (int i = blockIdx.x * 256 + tid; i < NWEI; i += 256 * 256)
        s += fabsf(w[i]);
    sm[tid] = s;
    __syncthreads();
    #pragma unroll
    for (int o = 128; o > 0; o >>= 1) {
        if (tid < o) sm[tid] += sm[tid + o];
        __syncthreads();
    }
    if (tid == 0) g_part[blockIdx.x] = sm[0];
}

__global__ void abssum_fin() {
    __shared__ float sm[256];
    const int tid = threadIdx.x;
    sm[tid] = g_part[tid];
    __syncthreads();
    #pragma unroll
    for (int o = 128; o > 0; o >>= 1) {
        if (tid < o) sm[tid] += sm[tid + o];
        __syncthreads();
    }
    if (tid == 0) g_alpha = sm[0] / (float)NWEI;
}

// ---------------------------------------------------------------------------
// Stage 2a: ternary quantize, OIHW -> [kb64][oc][64] fp16
// ---------------------------------------------------------------------------
__global__ void quantize_w(const float* __restrict__ w) {
    const int j = blockIdx.x * 256 + threadIdx.x;
    if (j >= NWEI) return;
    const float thr = 0.001f * g_alpha;
    const int oc  = j / KTOT;
    const int r   = j - oc * KTOT;
    const int tap = r / IC;
    const int ic  = r - tap * IC;
    const float wv = w[oc * KTOT + ic * 9 + tap];     // OIHW linear
    const float q = (wv > thr) ? 1.f : ((wv < -thr) ? -1.f : 0.f);
    const int kb = tap * 6 + (ic >> 6);
    g_wq[((size_t)kb * OCC + oc) * BK + (ic & 63)] = __float2half_rn(q);
}

// ---------------------------------------------------------------------------
// Stage 2b: x fp32 -> fp16, deinterleaved by kw tap, padded halo rows.
//   xq[kw][bc][row][ox] = x[bc][row-1][2*ox-1+kw]  (OOB -> 0)
// ---------------------------------------------------------------------------
__global__ void prep_x(const float* __restrict__ x) {
    const int idx = blockIdx.x * 256 + threadIdx.x;
    const int t = idx & 15;             // handles ox pair (2t, 2t+1)
    const int r = idx >> 4;             // row id over NB*IC*65
    if (r >= NB * IC * 65) return;
    const int iy = r % 65 - 1;          // -1..63
    const int bc = r / 65;              // b*IC + ic
    const size_t orow = ((size_t)bc * 66 + (iy + 1)) * 32 + 2 * t;

    __half2 h0, h1, h2;
    if (iy < 0) {
        h0 = h1 = h2 = __floats2half2_rn(0.f, 0.f);
    } else {
        const float* xr = x + ((size_t)bc * IH + iy) * IW;
        const float4 v = *reinterpret_cast<const float4*>(xr + 4 * t);
        const float prev = (t > 0) ? xr[4 * t - 1] : 0.f;
        h0 = __floats2half2_rn(prev, v.y);   // kw=0: ix = 2ox-1
        h1 = __floats2half2_rn(v.x,  v.z);   // kw=1: ix = 2ox
        h2 = __floats2half2_rn(v.y,  v.w);   // kw=2: ix = 2ox+1
    }
    *reinterpret_cast<__half2*>(g_xq + 0 * KWSZ + orow) = h0;
    *reinterpret_cast<__half2*>(g_xq + 1 * KWSZ + orow) = h1;
    *reinterpret_cast<__half2*>(g_xq + 2 * KWSZ + orow) = h2;
}

// ---------------------------------------------------------------------------
// Stage 3: persistent implicit-GEMM conv, cp.async S=3 + ldmatrix + mma.sync
// ---------------------------------------------------------------------------
__device__ __forceinline__ void cp16(uint32_t dst, const void* src) {
    asm volatile("cp.async.cg.shared.global [%0], [%1], 16;\n"
                 :: "r"(dst), "l"(src) : "memory");
}
__device__ __forceinline__ void ldsmA(uint32_t* f, uint32_t addr) {
    asm volatile("ldmatrix.sync.aligned.m8n8.x4.shared.b16 {%0,%1,%2,%3}, [%4];\n"
                 : "=r"(f[0]), "=r"(f[1]), "=r"(f[2]), "=r"(f[3]) : "r"(addr));
}
__device__ __forceinline__ void ldsmBT(uint32_t* f, uint32_t addr) {
    asm volatile("ldmatrix.sync.aligned.m8n8.x4.trans.shared.b16 {%0,%1,%2,%3}, [%4];\n"
                 : "=r"(f[0]), "=r"(f[1]), "=r"(f[2]), "=r"(f[3]) : "r"(addr));
}

__global__ __launch_bounds__(256, 2)
void conv_mma4(const float* __restrict__ bias, float* __restrict__ out)
{
    extern __shared__ char smem_raw[];
    const uint32_t sbase = (uint32_t)__cvta_generic_to_shared(smem_raw);

    const int tid  = threadIdx.x;
    const int lane = tid & 31;
    const int wid  = tid >> 5;
    const int wm   = wid >> 2;          // 0..1
    const int wn   = wid & 3;           // 0..3

    // ---- per-thread invariants (tile-independent) ----
    // A: chunk = tid + 256j (j<4): row = (tid>>3) + 32j, col-chunk c = tid&7
    const int am0 = tid >> 3, ac = tid & 7;
    const uint32_t adst0 = sbase + (uint32_t)(am0 * ASTR + ac * 8) * 2;
    // B: chunk = tid + 256j (j<4): row kB = (tid>>4) + 16j, col-chunk nc = tid&15
    const int kB0 = tid >> 4, nc = tid & 15;
    const uint32_t bdst0 = sbase + (uint32_t)ABYTES + (uint32_t)(kB0 * BSTR + nc * 8) * 2;
    const size_t   boff0 = (size_t)kB0 * (66 * 32) + (nc >> 2) * 64 + (nc & 3) * 8;

    // ldmatrix per-lane invariants
    const int arow  = wm * 64 + ((lane >> 3) & 1) * 8 + (lane & 7);
    const int acol  = (lane >> 4) * 8;
    const int brow  = ((lane >> 3) & 1) * 8 + (lane & 7);
    const int bcolh = wn * 32 + (lane >> 4) * 8;

    const int g  = lane >> 2;
    const int tq = lane & 3;
    const float alpha = g_alpha;

    #pragma unroll 1
    for (int tile = blockIdx.x; tile < NTILE; tile += GRID) {
        const int m_tile = tile % 3;        // consecutive tiles share B slab in L2
        const int n_tile = tile / 3;
        const int oc0  = m_tile * BM;
        const int n0   = n_tile * BN;
        const int bimg = n0 >> 10;
        const int pos0 = n0 & 1023;
        const int oy0  = pos0 >> 5;

        const size_t aoff0 = (size_t)(oc0 + am0) * BK + ac * 8;
        const size_t bbase = (size_t)bimg * IC * (66 * 32) + (size_t)(2 * oy0) * 32 + boff0;

        float acc[4][4][4];
        #pragma unroll
        for (int i = 0; i < 4; i++)
            #pragma unroll
            for (int j = 0; j < 4; j++)
                #pragma unroll
                for (int c = 0; c < 4; c++)
                    acc[i][j][c] = 0.f;

        auto issue = [&](int kb, int s) {
            const int tap = kb / 6;                  // 0..8
            const int icb = (kb - tap * 6) << 6;
            const int kh  = tap / 3;
            const int kw  = tap - kh * 3;
            const __half* wsrc = g_wq + (size_t)kb * (OCC * BK) + aoff0;
            const __half* xsrc = g_xq + (size_t)kw * KWSZ + bbase
                               + (size_t)icb * (66 * 32) + kh * 32;
            const uint32_t st = (uint32_t)(s * STAGE);
            #pragma unroll
            for (int j = 0; j < 4; j++)          // A rows am0 + 32j  (128 rows total)
                cp16(adst0 + st + j * (32 * ASTR * 2), wsrc + (size_t)j * (32 * BK));
            #pragma unroll
            for (int j = 0; j < 4; j++)          // B rows kB0 + 16j  (64 k-rows total)
                cp16(bdst0 + st + j * (16 * BSTR * 2), xsrc + (size_t)j * (16 * 66 * 32));
            asm volatile("cp.async.commit_group;\n" ::: "memory");
        };

        auto compute = [&](int s) {
            const uint32_t aB = sbase + (uint32_t)(s * STAGE);
            const uint32_t bB = aB + (uint32_t)ABYTES;
            #pragma unroll
            for (int step = 0; step < 4; step++) {
                uint32_t a[4][4], b[2][4];
                #pragma unroll
                for (int ms = 0; ms < 4; ms++)
                    ldsmA(a[ms], aB + (uint32_t)(((arow + ms * 16) * ASTR)
                                                 + step * 16 + acol) * 2);
                #pragma unroll
                for (int nb = 0; nb < 2; nb++)
                    ldsmBT(b[nb], bB + (uint32_t)((step * 16 + brow) * BSTR
                                                  + bcolh + nb * 16) * 2);
                #pragma unroll
                for (int ms = 0; ms < 4; ms++)
                    #pragma unroll
                    for (int ns = 0; ns < 4; ns++)
                        asm volatile(
                            "mma.sync.aligned.m16n8k16.row.col.f32.f16.f16.f32 "
                            "{%0,%1,%2,%3}, {%4,%5,%6,%7}, {%8,%9}, {%0,%1,%2,%3};\n"
                            : "+f"(acc[ms][ns][0]), "+f"(acc[ms][ns][1]),
                              "+f"(acc[ms][ns][2]), "+f"(acc[ms][ns][3])
                            : "r"(a[ms][0]), "r"(a[ms][1]), "r"(a[ms][2]), "r"(a[ms][3]),
                              "r"(b[ns >> 1][(ns & 1) * 2]),
                              "r"(b[ns >> 1][(ns & 1) * 2 + 1]));
            }
        };

        // prologue: fill S-1 stages
        issue(0, 0); issue(1, 1);

        #pragma unroll 1
        for (int kb = 0; kb < NKB; kb++) {
            asm volatile("cp.async.wait_group %0;\n" :: "n"(S - 2) : "memory");
            __syncthreads();
            if (kb + (S - 1) < NKB)
                issue(kb + (S - 1), (kb + (S - 1)) % S);
            else
                asm volatile("cp.async.commit_group;\n" ::: "memory");  // keep count exact
            compute(kb % S);
        }

        // epilogue: out = alpha*acc + bias (regs->gmem only; no smem hazard)
        float* ob = out + (size_t)bimg * OCC * (OH * OW);
        #pragma unroll
        for (int ms = 0; ms < 4; ms++) {
            const int oc_a = oc0 + wm * 64 + ms * 16 + g;
            const int oc_b = oc_a + 8;
            const float ba = bias[oc_a];
            const float bc = bias[oc_b];
            #pragma unroll
            for (int ns = 0; ns < 4; ns++) {
                const int pcol = pos0 + wn * 32 + ns * 8 + tq * 2;
                float2 v0, v1;
                v0.x = alpha * acc[ms][ns][0] + ba;
                v0.y = alpha * acc[ms][ns][1] + ba;
                v1.x = alpha * acc[ms][ns][2] + bc;
                v1.y = alpha * acc[ms][ns][3] + bc;
                *reinterpret_cast<float2*>(ob + (size_t)oc_a * (OH * OW) + pcol) = v0;
                *reinterpret_cast<float2*>(ob + (size_t)oc_b * (OH * OW) + pcol) = v1;
            }
        }
    }
}

// ---------------------------------------------------------------------------
extern "C" void kernel_launch(void* const* d_in, const int* in_sizes, int n_in,
                              void* d_out, int out_size)
{
    (void)in_sizes; (void)n_in; (void)out_size;
    const float* x      = (const float*)d_in[0];
    const float* weight = (const float*)d_in[1];
    const float* bias   = (const float*)d_in[2];
    float* out = (float*)d_out;

    cudaFuncSetAttribute(conv_mma4, cudaFuncAttributeMaxDynamicSharedMemorySize, SMEM_TOTAL);

    abssum_part<<<256, 256>>>(weight);
    abssum_fin<<<1, 256>>>();
    quantize_w<<<(NWEI + 255) / 256, 256>>>(weight);
    prep_x<<<(NB * IC * 65 * 16 + 255) / 256, 256>>>(x);
    conv_mma4<<<GRID, 256, SMEM_TOTAL>>>(bias, out);
}

// round 8
// speedup vs baseline: 1.0438x; 1.0162x over previous
#include <cuda_runtime.h>
#include <cuda_fp16.h>
#include <stdint.h>

// Problem constants
#define IC    384
#define OCC   384
#define NB    32
#define IH    64
#define IW    64
#define OH    32
#define OW    32
#define KTOT  (IC * 9)          // 3456
#define NWEI  (OCC * KTOT)      // 1327104
#define NTOT  (NB * OH * OW)    // 32768

// GEMM tiling: CTA = 128(M) x 128(N) x 32(K), 8 warps of 64x32, occupancy 2
#define BM    128
#define BN    128
#define BK    32
#define NKB   (KTOT / BK)       // 108
#define NTILE ((NTOT / BN) * 3) // 768 logical tiles
#define GRID  296               // persistent: 2 CTAs x 148 SMs
#define S     5                 // cp.async pipeline stages
#define ASTR  40                // halves per A smem row (80B, 16B-aligned, LDSM CF)
#define BSTR  136               // halves per B smem row (272B = 17 odd units, LDSM CF)
#define ABYTES (BM * ASTR * 2)  // 10240
#define BBYTES (BK * BSTR * 2)  // 8704
#define STAGE  (ABYTES + BBYTES)          // 18944
#define SMEM_TOTAL (S * STAGE)            // 94720 (x2 CTAs = 189KB/SM)

#define KWSZ ((size_t)NB * IC * 66 * 32)  // halves per kw plane
#define PREP_BLOCKS 49920                 // NB*IC*65*16/256
#define QUANT_BLOCKS 5184                 // ceil(NWEI/256)

// Scratch (device globals: allocation-free contract)
__device__ float  g_alpha;
__device__ float  g_part[256];
__device__ __half g_wq[(size_t)NKB * OCC * BK];  // [kb32][oc][32] ternary fp16
__device__ __half g_xq[3 * KWSZ];                // [kw][b][ic][row 0..65][ox 0..31]

// ---------------------------------------------------------------------------
// Stage 1: deterministic |w| reduction -> alpha
// ---------------------------------------------------------------------------
__global__ void abssum_part(const float* __restrict__ w) {
    __shared__ float sm[256];
    const int tid = threadIdx.x;
    float s = 0.f;
    for (int i = blockIdx.x * 256 + tid; i < NWEI; i += 256 * 256)
        s += fabsf(w[i]);
    sm[tid] = s;
    __syncthreads();
    #pragma unroll
    for (int o = 128; o > 0; o >>= 1) {
        if (tid < o) sm[tid] += sm[tid + o];
        __syncthreads();
    }
    if (tid == 0) g_part[blockIdx.x] = sm[0];
}

__global__ void abssum_fin() {
    __shared__ float sm[256];
    const int tid = threadIdx.x;
    sm[tid] = g_part[tid];
    __syncthreads();
    #pragma unroll
    for (int o = 128; o > 0; o >>= 1) {
        if (tid < o) sm[tid] += sm[tid + o];
        __syncthreads();
    }
    if (tid == 0) g_alpha = sm[0] / (float)NWEI;
}

// ---------------------------------------------------------------------------
// Stage 2 (merged): ternary quantize + x fp16 prep, one launch.
//   bid <  PREP_BLOCKS : xq[kw][bc][row][ox] = x[bc][row-1][2ox-1+kw] (OOB->0)
//   bid >= PREP_BLOCKS : g_wq[kb][oc][32] ternary from OIHW weights
// ---------------------------------------------------------------------------
__global__ void prep_and_quant(const float* __restrict__ x,
                               const float* __restrict__ w) {
    const int tid = threadIdx.x;
    if (blockIdx.x < PREP_BLOCKS) {
        const int idx = blockIdx.x * 256 + tid;
        const int t = idx & 15;             // ox pair (2t, 2t+1)
        const int r = idx >> 4;             // row id over NB*IC*65
        const int iy = r % 65 - 1;          // -1..63
        const int bc = r / 65;              // b*IC + ic
        const size_t orow = ((size_t)bc * 66 + (iy + 1)) * 32 + 2 * t;

        __half2 h0, h1, h2;
        if (iy < 0) {
            h0 = h1 = h2 = __floats2half2_rn(0.f, 0.f);
        } else {
            const float* xr = x + ((size_t)bc * IH + iy) * IW;
            const float4 v = *reinterpret_cast<const float4*>(xr + 4 * t);
            const float prev = (t > 0) ? xr[4 * t - 1] : 0.f;
            h0 = __floats2half2_rn(prev, v.y);   // kw=0: ix = 2ox-1
            h1 = __floats2half2_rn(v.x,  v.z);   // kw=1: ix = 2ox
            h2 = __floats2half2_rn(v.y,  v.w);   // kw=2: ix = 2ox+1
        }
        *reinterpret_cast<__half2*>(g_xq + 0 * KWSZ + orow) = h0;
        *reinterpret_cast<__half2*>(g_xq + 1 * KWSZ + orow) = h1;
        *reinterpret_cast<__half2*>(g_xq + 2 * KWSZ + orow) = h2;
    } else {
        const int j = (blockIdx.x - PREP_BLOCKS) * 256 + tid;
        if (j >= NWEI) return;
        const float thr = 0.001f * g_alpha;
        const int oc  = j / KTOT;
        const int r   = j - oc * KTOT;
        const int tap = r / IC;
        const int ic  = r - tap * IC;
        const float wv = w[oc * KTOT + ic * 9 + tap];     // OIHW linear
        const float q = (wv > thr) ? 1.f : ((wv < -thr) ? -1.f : 0.f);
        const int kb = tap * 12 + (ic >> 5);
        g_wq[((size_t)kb * OCC + oc) * BK + (ic & 31)] = __float2half_rn(q);
    }
}

// ---------------------------------------------------------------------------
// Stage 3: persistent implicit-GEMM conv, cp.async S=5 + ldmatrix + mma.sync
// ---------------------------------------------------------------------------
__device__ __forceinline__ void cp16(uint32_t dst, const void* src) {
    asm volatile("cp.async.cg.shared.global [%0], [%1], 16;\n"
                 :: "r"(dst), "l"(src) : "memory");
}
__device__ __forceinline__ void ldsmA(uint32_t* f, uint32_t addr) {
    asm volatile("ldmatrix.sync.aligned.m8n8.x4.shared.b16 {%0,%1,%2,%3}, [%4];\n"
                 : "=r"(f[0]), "=r"(f[1]), "=r"(f[2]), "=r"(f[3]) : "r"(addr));
}
__device__ __forceinline__ void ldsmBT(uint32_t* f, uint32_t addr) {
    asm volatile("ldmatrix.sync.aligned.m8n8.x4.trans.shared.b16 {%0,%1,%2,%3}, [%4];\n"
                 : "=r"(f[0]), "=r"(f[1]), "=r"(f[2]), "=r"(f[3]) : "r"(addr));
}

__global__ __launch_bounds__(256, 2)
void conv_mma5(const float* __restrict__ bias, float* __restrict__ out)
{
    extern __shared__ char smem_raw[];
    const uint32_t sbase = (uint32_t)__cvta_generic_to_shared(smem_raw);

    const int tid  = threadIdx.x;
    const int lane = tid & 31;
    const int wid  = tid >> 5;
    const int wm   = wid >> 2;          // 0..1
    const int wn   = wid & 3;           // 0..3

    // ---- per-thread invariants (tile-independent) ----
    // A: chunk = tid + 256j (j<2): m = chunk>>2 (0..127), c = chunk&3
    //    (tid&3 const over j; m jumps +64 per j)
    const int am0 = tid >> 2, ac = tid & 3;
    const uint32_t adst0 = sbase + (uint32_t)(am0 * ASTR + ac * 8) * 2;
    // B: slot = tid + 256j (j<2): kB = slot>>4 (+16/j), nc = tid&15 const
    const int kB0 = tid >> 4, nc = tid & 15;
    const uint32_t bdst0 = sbase + (uint32_t)ABYTES + (uint32_t)(kB0 * BSTR + nc * 8) * 2;

    // ldmatrix per-lane invariants
    const int arow  = wm * 64 + ((lane >> 3) & 1) * 8 + (lane & 7);
    const int acol  = (lane >> 4) * 8;
    const int brow  = ((lane >> 3) & 1) * 8 + (lane & 7);
    const int bcolh = wn * 32 + (lane >> 4) * 8;

    const int g  = lane >> 2;
    const int tq = lane & 3;
    const float alpha = g_alpha;

    #pragma unroll 1
    for (int tile = blockIdx.x; tile < NTILE; tile += GRID) {
        const int m_tile = tile % 3;        // consecutive tiles share B slab in L2
        const int n_tile = tile / 3;
        const int oc0  = m_tile * BM;
        const int n0   = n_tile * BN;
        const int bimg = n0 >> 10;
        const int pos0 = n0 & 1023;
        const int oy0  = pos0 >> 5;

        const size_t aoff0 = (size_t)(oc0 + am0) * BK + ac * 8;
        const int    oyc   = oy0 + (nc >> 2);
        const size_t boff0 = ((size_t)(bimg * IC + kB0) * 66 + 2 * oyc) * 32 + (nc & 3) * 8;

        float acc[4][4][4];
        #pragma unroll
        for (int i = 0; i < 4; i++)
            #pragma unroll
            for (int j = 0; j < 4; j++)
                #pragma unroll
                for (int c = 0; c < 4; c++)
                    acc[i][j][c] = 0.f;

        auto issue = [&](int kb, int s) {
            const int tap = kb / 12;                 // 0..8
            const int icb = (kb - tap * 12) << 5;
            const int kh  = tap / 3;
            const int kw  = tap - kh * 3;
            const __half* wsrc = g_wq + (size_t)kb * (OCC * BK) + aoff0;
            const __half* xsrc = g_xq + (size_t)kw * KWSZ + boff0
                               + (size_t)icb * (66 * 32) + kh * 32;
            const uint32_t st = (uint32_t)(s * STAGE);
            cp16(adst0 + st,                     wsrc);
            cp16(adst0 + st + (64 * ASTR * 2),   wsrc + 64 * BK);
            cp16(bdst0 + st,                     xsrc);
            cp16(bdst0 + st + (16 * BSTR * 2),   xsrc + (size_t)16 * (66 * 32));
            asm volatile("cp.async.commit_group;\n" ::: "memory");
        };

        auto compute = [&](int s) {
            const uint32_t aB = sbase + (uint32_t)(s * STAGE);
            const uint32_t bB = aB + (uint32_t)ABYTES;
            #pragma unroll
            for (int step = 0; step < 2; step++) {
                uint32_t a[4][4], b[2][4];
                #pragma unroll
                for (int ms = 0; ms < 4; ms++)
                    ldsmA(a[ms], aB + (uint32_t)(((arow + ms * 16) * ASTR)
                                                 + step * 16 + acol) * 2);
                #pragma unroll
                for (int nb = 0; nb < 2; nb++)
                    ldsmBT(b[nb], bB + (uint32_t)((step * 16 + brow) * BSTR
                                                  + bcolh + nb * 16) * 2);
                #pragma unroll
                for (int ms = 0; ms < 4; ms++)
                    #pragma unroll
                    for (int ns = 0; ns < 4; ns++)
                        asm volatile(
                            "mma.sync.aligned.m16n8k16.row.col.f32.f16.f16.f32 "
                            "{%0,%1,%2,%3}, {%4,%5,%6,%7}, {%8,%9}, {%0,%1,%2,%3};\n"
                            : "+f"(acc[ms][ns][0]), "+f"(acc[ms][ns][1]),
                              "+f"(acc[ms][ns][2]), "+f"(acc[ms][ns][3])
                            : "r"(a[ms][0]), "r"(a[ms][1]), "r"(a[ms][2]), "r"(a[ms][3]),
                              "r"(b[ns >> 1][(ns & 1) * 2]),
                              "r"(b[ns >> 1][(ns & 1) * 2 + 1]));
            }
        };

        // tile boundary: with S>=4 the prologue below rewrites stages that
        // straggler warps of the previous tile may still be reading
        __syncthreads();

        // prologue: fill S-1 stages
        #pragma unroll
        for (int p = 0; p < S - 1; p++) issue(p, p);

        #pragma unroll 1
        for (int kb = 0; kb < NKB; kb++) {
            asm volatile("cp.async.wait_group %0;\n" :: "n"(S - 2) : "memory");
            __syncthreads();
            if (kb + (S - 1) < NKB)
                issue(kb + (S - 1), (kb + (S - 1)) % S);
            else
                asm volatile("cp.async.commit_group;\n" ::: "memory");  // keep count exact
            compute(kb % S);
        }

        // epilogue: out = alpha*acc + bias (regs->gmem only; no smem hazard)
        float* ob = out + (size_t)bimg * OCC * (OH * OW);
        #pragma unroll
        for (int ms = 0; ms < 4; ms++) {
            const int oc_a = oc0 + wm * 64 + ms * 16 + g;
            const int oc_b = oc_a + 8;
            const float ba = bias[oc_a];
            const float bc = bias[oc_b];
            #pragma unroll
            for (int ns = 0; ns < 4; ns++) {
                const int pcol = pos0 + wn * 32 + ns * 8 + tq * 2;
                float2 v0, v1;
                v0.x = alpha * acc[ms][ns][0] + ba;
                v0.y = alpha * acc[ms][ns][1] + ba;
                v1.x = alpha * acc[ms][ns][2] + bc;
                v1.y = alpha * acc[ms][ns][3] + bc;
                *reinterpret_cast<float2*>(ob + (size_t)oc_a * (OH * OW) + pcol) = v0;
                *reinterpret_cast<float2*>(ob + (size_t)oc_b * (OH * OW) + pcol) = v1;
            }
        }
    }
}

// ---------------------------------------------------------------------------
extern "C" void kernel_launch(void* const* d_in, const int* in_sizes, int n_in,
                              void* d_out, int out_size)
{
    (void)in_sizes; (void)n_in; (void)out_size;
    const float* x      = (const float*)d_in[0];
    const float* weight = (const float*)d_in[1];
    const float* bias   = (const float*)d_in[2];
    float* out = (float*)d_out;

    cudaFuncSetAttribute(conv_mma5, cudaFuncAttributeMaxDynamicSharedMemorySize, SMEM_TOTAL);

    abssum_part<<<256, 256>>>(weight);                        // launch 1
    abssum_fin<<<1, 256>>>();                                 // launch 2
    prep_and_quant<<<PREP_BLOCKS + QUANT_BLOCKS, 256>>>(x, weight);  // launch 3
    conv_mma5<<<GRID, 256, SMEM_TOTAL>>>(bias, out);          // launch 4 -> ncu captures this
}

// round 9
// speedup vs baseline: 1.0588x; 1.0144x over previous
#include <cuda_runtime.h>
#include <cuda_fp16.h>
#include <stdint.h>

// Problem constants
#define IC    384
#define OCC   384
#define NB    32
#define IH    64
#define IW    64
#define OH    32
#define OW    32
#define KTOT  (IC * 9)          // 3456
#define NWEI  (OCC * KTOT)      // 1327104
#define NTOT  (NB * OH * OW)    // 32768

// GEMM tiling: CTA = 128(M) x 128(N) x 32(K), 8 warps of 64x32, occupancy 2
#define BM    128
#define BN    128
#define BK    32
#define NKB   (KTOT / BK)       // 108
#define NTILE ((NTOT / BN) * 3) // 768 logical tiles
#define GRID  296               // persistent: 2 CTAs x 148 SMs
#define S     5                 // cp.async pipeline stages
#define ASTR  40                // halves per A smem row (80B, 16B-aligned, LDSM CF)
#define BSTR  136               // halves per B smem row (272B = 17 odd units, LDSM CF)
#define ABYTES (BM * ASTR * 2)  // 10240
#define BBYTES (BK * BSTR * 2)  // 8704
#define STAGE  (ABYTES + BBYTES)          // 18944
#define SMEM_TOTAL (S * STAGE)            // 94720 (x2 CTAs = 189KB/SM)

#define KWSZ ((size_t)NB * IC * 66 * 32)  // halves per kw plane
#define PREP_BLOCKS 49920                 // NB*IC*65*16/256
#define QUANT_BLOCKS 5184                 // ceil(NWEI/256)

// Scratch (device globals: allocation-free contract)
__device__ float  g_alpha;
__device__ float  g_part[256];
__device__ __half g_wq[(size_t)NKB * OCC * BK];  // [kb32][oc][32] ternary fp16
__device__ __half g_xq[3 * KWSZ];                // [kw][b][ic][row 0..65][ox 0..31]

// ---------------------------------------------------------------------------
// Stage 1: deterministic |w| reduction -> alpha
// ---------------------------------------------------------------------------
__global__ void abssum_part(const float* __restrict__ w) {
    __shared__ float sm[256];
    const int tid = threadIdx.x;
    float s = 0.f;
    for (int i = blockIdx.x * 256 + tid; i < NWEI; i += 256 * 256)
        s += fabsf(w[i]);
    sm[tid] = s;
    __syncthreads();
    #pragma unroll
    for (int o = 128; o > 0; o >>= 1) {
        if (tid < o) sm[tid] += sm[tid + o];
        __syncthreads();
    }
    if (tid == 0) g_part[blockIdx.x] = sm[0];
}

__global__ void abssum_fin() {
    __shared__ float sm[256];
    const int tid = threadIdx.x;
    sm[tid] = g_part[tid];
    __syncthreads();
    #pragma unroll
    for (int o = 128; o > 0; o >>= 1) {
        if (tid < o) sm[tid] += sm[tid + o];
        __syncthreads();
    }
    if (tid == 0) g_alpha = sm[0] / (float)NWEI;
}

// ---------------------------------------------------------------------------
// Stage 2 (merged): ternary quantize + x fp16 prep, one launch.
// ---------------------------------------------------------------------------
__global__ void prep_and_quant(const float* __restrict__ x,
                               const float* __restrict__ w) {
    const int tid = threadIdx.x;
    if (blockIdx.x < PREP_BLOCKS) {
        const int idx = blockIdx.x * 256 + tid;
        const int t = idx & 15;             // ox pair (2t, 2t+1)
        const int r = idx >> 4;             // row id over NB*IC*65
        const int iy = r % 65 - 1;          // -1..63
        const int bc = r / 65;              // b*IC + ic
        const size_t orow = ((size_t)bc * 66 + (iy + 1)) * 32 + 2 * t;

        __half2 h0, h1, h2;
        if (iy < 0) {
            h0 = h1 = h2 = __floats2half2_rn(0.f, 0.f);
        } else {
            const float* xr = x + ((size_t)bc * IH + iy) * IW;
            const float4 v = *reinterpret_cast<const float4*>(xr + 4 * t);
            const float prev = (t > 0) ? xr[4 * t - 1] : 0.f;
            h0 = __floats2half2_rn(prev, v.y);   // kw=0: ix = 2ox-1
            h1 = __floats2half2_rn(v.x,  v.z);   // kw=1: ix = 2ox
            h2 = __floats2half2_rn(v.y,  v.w);   // kw=2: ix = 2ox+1
        }
        *reinterpret_cast<__half2*>(g_xq + 0 * KWSZ + orow) = h0;
        *reinterpret_cast<__half2*>(g_xq + 1 * KWSZ + orow) = h1;
        *reinterpret_cast<__half2*>(g_xq + 2 * KWSZ + orow) = h2;
    } else {
        const int j = (blockIdx.x - PREP_BLOCKS) * 256 + tid;
        if (j >= NWEI) return;
        const float thr = 0.001f * g_alpha;
        const int oc  = j / KTOT;
        const int r   = j - oc * KTOT;
        const int tap = r / IC;
        const int ic  = r - tap * IC;
        const float wv = w[oc * KTOT + ic * 9 + tap];     // OIHW linear
        const float q = (wv > thr) ? 1.f : ((wv < -thr) ? -1.f : 0.f);
        const int kb = tap * 12 + (ic >> 5);
        g_wq[((size_t)kb * OCC + oc) * BK + (ic & 31)] = __float2half_rn(q);
    }
}

// ---------------------------------------------------------------------------
// Stage 3: persistent implicit-GEMM conv, cp.async S=5 + ldmatrix + mma.sync
//   warp-parity step skew: odd warps run k16-steps in reverse order so the
//   LDSM burst of half the warps overlaps the HMMA stream of the other half
// ---------------------------------------------------------------------------
__device__ __forceinline__ void cp16(uint32_t dst, const void* src) {
    asm volatile("cp.async.cg.shared.global [%0], [%1], 16;\n"
                 :: "r"(dst), "l"(src) : "memory");
}
__device__ __forceinline__ void ldsmA(uint32_t* f, uint32_t addr) {
    asm volatile("ldmatrix.sync.aligned.m8n8.x4.shared.b16 {%0,%1,%2,%3}, [%4];\n"
                 : "=r"(f[0]), "=r"(f[1]), "=r"(f[2]), "=r"(f[3]) : "r"(addr));
}
__device__ __forceinline__ void ldsmBT(uint32_t* f, uint32_t addr) {
    asm volatile("ldmatrix.sync.aligned.m8n8.x4.trans.shared.b16 {%0,%1,%2,%3}, [%4];\n"
                 : "=r"(f[0]), "=r"(f[1]), "=r"(f[2]), "=r"(f[3]) : "r"(addr));
}

__global__ __launch_bounds__(256, 2)
void conv_mma6(const float* __restrict__ bias, float* __restrict__ out)
{
    extern __shared__ char smem_raw[];
    const uint32_t sbase = (uint32_t)__cvta_generic_to_shared(smem_raw);

    const int tid  = threadIdx.x;
    const int lane = tid & 31;
    const int wid  = tid >> 5;
    const int wm   = wid >> 2;          // 0..1
    const int wn   = wid & 3;           // 0..3
    const int wpar = wid & 1;           // step-order parity

    // ---- per-thread invariants (tile-independent) ----
    const int am0 = tid >> 2, ac = tid & 3;
    const uint32_t adst0 = sbase + (uint32_t)(am0 * ASTR + ac * 8) * 2;
    const int kB0 = tid >> 4, nc = tid & 15;
    const uint32_t bdst0 = sbase + (uint32_t)ABYTES + (uint32_t)(kB0 * BSTR + nc * 8) * 2;

    // ldmatrix per-lane invariants
    const int arow  = wm * 64 + ((lane >> 3) & 1) * 8 + (lane & 7);
    const int acol  = (lane >> 4) * 8;
    const int brow  = ((lane >> 3) & 1) * 8 + (lane & 7);
    const int bcolh = wn * 32 + (lane >> 4) * 8;

    const int g  = lane >> 2;
    const int tq = lane & 3;
    const float alpha = g_alpha;

    #pragma unroll 1
    for (int tile = blockIdx.x; tile < NTILE; tile += GRID) {
        const int m_tile = tile % 3;        // consecutive tiles share B slab in L2
        const int n_tile = tile / 3;
        const int oc0  = m_tile * BM;
        const int n0   = n_tile * BN;
        const int bimg = n0 >> 10;
        const int pos0 = n0 & 1023;
        const int oy0  = pos0 >> 5;

        const size_t aoff0 = (size_t)(oc0 + am0) * BK + ac * 8;
        const int    oyc   = oy0 + (nc >> 2);
        const size_t boff0 = ((size_t)(bimg * IC + kB0) * 66 + 2 * oyc) * 32 + (nc & 3) * 8;

        float acc[4][4][4];
        #pragma unroll
        for (int i = 0; i < 4; i++)
            #pragma unroll
            for (int j = 0; j < 4; j++)
                #pragma unroll
                for (int c = 0; c < 4; c++)
                    acc[i][j][c] = 0.f;

        auto issue = [&](int kb, int s) {
            const int tap = kb / 12;                 // 0..8
            const int icb = (kb - tap * 12) << 5;
            const int kh  = tap / 3;
            const int kw  = tap - kh * 3;
            const __half* wsrc = g_wq + (size_t)kb * (OCC * BK) + aoff0;
            const __half* xsrc = g_xq + (size_t)kw * KWSZ + boff0
                               + (size_t)icb * (66 * 32) + kh * 32;
            const uint32_t st = (uint32_t)(s * STAGE);
            cp16(adst0 + st,                     wsrc);
            cp16(adst0 + st + (64 * ASTR * 2),   wsrc + 64 * BK);
            cp16(bdst0 + st,                     xsrc);
            cp16(bdst0 + st + (16 * BSTR * 2),   xsrc + (size_t)16 * (66 * 32));
            asm volatile("cp.async.commit_group;\n" ::: "memory");
        };

        auto do_step = [&](uint32_t aB, uint32_t bB, int step) {
            uint32_t a[4][4], b[2][4];
            // interleave A/B ldmatrix to spread L1 wavefronts
            ldsmA(a[0], aB + (uint32_t)(((arow + 0 * 16) * ASTR) + step * 16 + acol) * 2);
            ldsmBT(b[0], bB + (uint32_t)((step * 16 + brow) * BSTR + bcolh) * 2);
            ldsmA(a[1], aB + (uint32_t)(((arow + 1 * 16) * ASTR) + step * 16 + acol) * 2);
            ldsmBT(b[1], bB + (uint32_t)((step * 16 + brow) * BSTR + bcolh + 16) * 2);
            ldsmA(a[2], aB + (uint32_t)(((arow + 2 * 16) * ASTR) + step * 16 + acol) * 2);
            ldsmA(a[3], aB + (uint32_t)(((arow + 3 * 16) * ASTR) + step * 16 + acol) * 2);
            #pragma unroll
            for (int ms = 0; ms < 4; ms++)
                #pragma unroll
                for (int ns = 0; ns < 4; ns++)
                    asm volatile(
                        "mma.sync.aligned.m16n8k16.row.col.f32.f16.f16.f32 "
                        "{%0,%1,%2,%3}, {%4,%5,%6,%7}, {%8,%9}, {%0,%1,%2,%3};\n"
                        : "+f"(acc[ms][ns][0]), "+f"(acc[ms][ns][1]),
                          "+f"(acc[ms][ns][2]), "+f"(acc[ms][ns][3])
                        : "r"(a[ms][0]), "r"(a[ms][1]), "r"(a[ms][2]), "r"(a[ms][3]),
                          "r"(b[ns >> 1][(ns & 1) * 2]),
                          "r"(b[ns >> 1][(ns & 1) * 2 + 1]));
        };

        auto compute = [&](int s) {
            const uint32_t aB = sbase + (uint32_t)(s * STAGE);
            const uint32_t bB = aB + (uint32_t)ABYTES;
            // warp-parity skew: odd warps take steps in reverse order
            if (wpar == 0) { do_step(aB, bB, 0); do_step(aB, bB, 1); }
            else           { do_step(aB, bB, 1); do_step(aB, bB, 0); }
        };

        // tile boundary: prologue below rewrites stages that straggler warps
        // of the previous tile may still be reading
        __syncthreads();

        // prologue: fill S-1 stages
        #pragma unroll
        for (int p = 0; p < S - 1; p++) issue(p, p);

        #pragma unroll 1
        for (int kb = 0; kb < NKB; kb++) {
            asm volatile("cp.async.wait_group %0;\n" :: "n"(S - 2) : "memory");
            __syncthreads();
            if (kb + (S - 1) < NKB)
                issue(kb + (S - 1), (kb + (S - 1)) % S);
            else
                asm volatile("cp.async.commit_group;\n" ::: "memory");  // keep count exact
            compute(kb % S);
        }

        // epilogue: out = alpha*acc + bias (regs->gmem only; no smem hazard)
        float* ob = out + (size_t)bimg * OCC * (OH * OW);
        #pragma unroll
        for (int ms = 0; ms < 4; ms++) {
            const int oc_a = oc0 + wm * 64 + ms * 16 + g;
            const int oc_b = oc_a + 8;
            const float ba = bias[oc_a];
            const float bc = bias[oc_b];
            #pragma unroll
            for (int ns = 0; ns < 4; ns++) {
                const int pcol = pos0 + wn * 32 + ns * 8 + tq * 2;
                float2 v0, v1;
                v0.x = alpha * acc[ms][ns][0] + ba;
                v0.y = alpha * acc[ms][ns][1] + ba;
                v1.x = alpha * acc[ms][ns][2] + bc;
                v1.y = alpha * acc[ms][ns][3] + bc;
                *reinterpret_cast<float2*>(ob + (size_t)oc_a * (OH * OW) + pcol) = v0;
                *reinterpret_cast<float2*>(ob + (size_t)oc_b * (OH * OW) + pcol) = v1;
            }
        }
    }
}

// ---------------------------------------------------------------------------
extern "C" void kernel_launch(void* const* d_in, const int* in_sizes, int n_in,
                              void* d_out, int out_size)
{
    (void)in_sizes; (void)n_in; (void)out_size;
    const float* x      = (const float*)d_in[0];
    const float* weight = (const float*)d_in[1];
    const float* bias   = (const float*)d_in[2];
    float* out = (float*)d_out;

    cudaFuncSetAttribute(conv_mma6, cudaFuncAttributeMaxDynamicSharedMemorySize, SMEM_TOTAL);

    abssum_part<<<256, 256>>>(weight);                        // launch 1
    abssum_fin<<<1, 256>>>();                                 // launch 2
    prep_and_quant<<<PREP_BLOCKS + QUANT_BLOCKS, 256>>>(x, weight);  // launch 3
    conv_mma6<<<GRID, 256, SMEM_TOTAL>>>(bias, out);          // launch 4 -> ncu captures this
}